// round 16
// baseline (speedup 1.0000x reference)
#include <cuda_runtime.h>
#include <cuda_bf16.h>
#include <math.h>

#define BATCH 2
#define NPTS  8192
#define CH    128
#define KNN   8
#define MTOT  (BATCH * NPTS)

// ---------------- scratch (no allocations allowed) ----------------
__device__ float g_q[MTOT * CH];
__device__ float g_k[MTOT * CH];
__device__ float g_v[MTOT * CH];
__device__ int   g_idx[MTOT * KNN];
__device__ uint4 g_agg2[MTOT * 64];    // agg split, X-pattern (hi,lo,hi,lo)

// ---------------- fp32 -> (hi,lo) bf16 split helpers ----------------
__device__ __forceinline__ void split_bf16(float x, unsigned short& h, unsigned short& l) {
    __nv_bfloat16 hb = __float2bfloat16(x);
    float hf = __bfloat162float(hb);
    __nv_bfloat16 lb = __float2bfloat16(x - hf);
    h = __bfloat16_as_ushort(hb);
    l = __bfloat16_as_ushort(lb);
}
__device__ __forceinline__ unsigned pack_hilo(float x) {   // X-pattern word (hi,lo)
    unsigned short h, l; split_bf16(x, h, l);
    return ((unsigned)l << 16) | (unsigned)h;
}
__device__ __forceinline__ void pack_w(float x, unsigned& p0, unsigned& p1) { // (hi,hi),(lo,lo)
    unsigned short h, l; split_bf16(x, h, l);
    p0 = ((unsigned)h << 16) | h;
    p1 = ((unsigned)l << 16) | l;
}

// ---------------- tensor-core GEMM:  Y = X @ W^T via bf16 split-K ----------------
// 64x128 CTA tile, 256 threads = 8 warps (2x4), warp tile 32x32, mma.m16n8k16.
// W fp32 split inline; X either fp32 (SPLIT_X) or pre-split uint4 X-pattern.
// smem rows padded to 144B -> conflict-free LDS.32 fragment loads.
template <bool SPLIT_X>
__device__ __forceinline__ void mma_gemm_tile(const void* __restrict__ Xv,
                                              const float* __restrict__ Wf,
                                              float* __restrict__ Y, int m0)
{
    __shared__ __align__(16) unsigned char xs[64 * 144];
    __shared__ __align__(16) unsigned char ws[128 * 144];
    const int tid  = threadIdx.x;
    const int lane = tid & 31;
    const int warp = tid >> 5;
    const int wm   = warp >> 2;       // 0..1 -> rows wm*32
    const int wn   = warp & 3;        // 0..3 -> cols wn*32
    const int g    = lane >> 2;       // 0..7
    const int c4   = lane & 3;        // 0..3

    float acc[2][4][4];
#pragma unroll
    for (int i = 0; i < 2; i++)
#pragma unroll
        for (int t = 0; t < 4; t++)
#pragma unroll
            for (int r = 0; r < 4; r++) acc[i][t][r] = 0.f;

    for (int kc = 0; kc < 8; kc++) {        // K' = 512 in chunks of 64
        __syncthreads();
#pragma unroll
        for (int i = 0; i < 2; i++) {
            int s  = tid + i * 256;
            int r  = s >> 3;
            int f4 = s & 7;
            if (SPLIT_X) {
                const float* X = (const float*)Xv;
                float2 xv = *(const float2*)(X + (size_t)(m0 + r) * CH + kc * 16 + f4 * 2);
                unsigned p0 = pack_hilo(xv.x), p1 = pack_hilo(xv.y);
                *(uint4*)(xs + r * 144 + f4 * 16) = make_uint4(p0, p0, p1, p1);
            } else {
                const uint4* X2 = (const uint4*)Xv;
                *(uint4*)(xs + r * 144 + f4 * 16) = X2[(size_t)(m0 + r) * 64 + kc * 8 + f4];
            }
        }
#pragma unroll
        for (int i = 0; i < 4; i++) {
            int s  = tid + i * 256;
            int r  = s >> 3;
            int f4 = s & 7;
            float2 wv = *(const float2*)(Wf + (size_t)r * CH + kc * 16 + f4 * 2);
            unsigned a0, a1, b0, b1;
            pack_w(wv.x, a0, a1);
            pack_w(wv.y, b0, b1);
            *(uint4*)(ws + r * 144 + f4 * 16) = make_uint4(a0, a1, b0, b1);
        }
        __syncthreads();
#pragma unroll
        for (int ks = 0; ks < 4; ks++) {    // 4 x k16 steps
            unsigned a[2][4], b[4][2];
#pragma unroll
            for (int i = 0; i < 2; i++)
#pragma unroll
                for (int j = 0; j < 4; j++) {
                    int row = wm * 32 + i * 16 + g + 8 * (j & 1);
                    int off = ks * 32 + (j >> 1) * 16 + c4 * 4;
                    a[i][j] = *(const unsigned*)(xs + row * 144 + off);
                }
#pragma unroll
            for (int t = 0; t < 4; t++)
#pragma unroll
                for (int r = 0; r < 2; r++) {
                    int n   = wn * 32 + t * 8 + g;
                    int off = ks * 32 + r * 16 + c4 * 4;
                    b[t][r] = *(const unsigned*)(ws + n * 144 + off);
                }
#pragma unroll
            for (int i = 0; i < 2; i++)
#pragma unroll
                for (int t = 0; t < 4; t++)
                    asm volatile(
                        "mma.sync.aligned.m16n8k16.row.col.f32.bf16.bf16.f32 "
                        "{%0,%1,%2,%3}, {%4,%5,%6,%7}, {%8,%9}, {%0,%1,%2,%3};"
                        : "+f"(acc[i][t][0]), "+f"(acc[i][t][1]),
                          "+f"(acc[i][t][2]), "+f"(acc[i][t][3])
                        : "r"(a[i][0]), "r"(a[i][1]), "r"(a[i][2]), "r"(a[i][3]),
                          "r"(b[t][0]), "r"(b[t][1]));
        }
    }
#pragma unroll
    for (int i = 0; i < 2; i++)
#pragma unroll
        for (int t = 0; t < 4; t++) {
            int row = m0 + wm * 32 + i * 16 + g;
            int col = wn * 32 + t * 8 + 2 * c4;
            *(float2*)(Y + (size_t)row * CH + col)       = make_float2(acc[i][t][0], acc[i][t][1]);
            *(float2*)(Y + (size_t)(row + 8) * CH + col) = make_float2(acc[i][t][2], acc[i][t][3]);
        }
}

__global__ __launch_bounds__(256) void qkv_mma_kernel(const float* __restrict__ feats,
                                                      const float* __restrict__ Wq,
                                                      const float* __restrict__ Wk,
                                                      const float* __restrict__ Wv)
{
    int w = blockIdx.y;
    const float* W = (w == 0) ? Wq : (w == 1) ? Wk : Wv;
    float* Y = (w == 0) ? g_q : (w == 1) ? g_k : g_v;
    mma_gemm_tile<true>(feats, W, Y, blockIdx.x * 64);
}

__global__ __launch_bounds__(256) void out_mma_kernel(const float* __restrict__ Wo,
                                                      float* __restrict__ out)
{
    mma_gemm_tile<false>(g_agg2, Wo, out, blockIdx.x * 64);
}

// ---------------- KNN: R14 scan, occupancy 3 to leave RF room for qkv ----------
// e-space ordering: e = csq - 2*dot (query-constant shift of d2; same top-k set).
// 3 CTAs/SM x 64 regs = 48K regs -> one qkv CTA (~20K regs, 37KB smem) co-resides.
#define QW  4
#define CCH 2048

__device__ __forceinline__ void try_insert4(float d2, int base,
                                            float& val, int& idx, float& thr)
{
    const unsigned full = 0xffffffffu;
    unsigned m = __ballot_sync(full, d2 < thr);
    const int lane = threadIdx.x & 31;
    while (m) {
        int src = __ffs(m) - 1;
        m &= m - 1;
        float dn = __shfl_sync(full, d2, src);
        if (dn < thr) {                         // warp-uniform
            int   in = base + (src << 2);
            float pv = __shfl_up_sync(full, val, 1);
            int   pi = __shfl_up_sync(full, idx, 1);
            unsigned le = __ballot_sync(full, val <= dn);
            int pos = __popc(le & 0xff);
            if (lane == pos)                  { val = dn; idx = in; }
            else if (lane > pos && lane < 8)  { val = pv; idx = pi; }
            thr = __shfl_sync(full, val, 7);
        }
    }
}

__global__ __launch_bounds__(256, 3) void knn_kernel(const float* __restrict__ coords,
                                                     int* __restrict__ out_idx)
{
    __shared__ float sx[CCH], sy[CCH], sz[CCH], ss[CCH];
    const unsigned full = 0xffffffffu;
    const int b     = blockIdx.y;
    const int warp  = threadIdx.x >> 5;
    const int lane  = threadIdx.x & 31;
    const int qbase = blockIdx.x * (8 * QW) + warp * QW;
    const float* cb = coords + (size_t)b * NPTS * 3;

    float m2x[QW], m2y[QW], m2z[QW];
#pragma unroll
    for (int u = 0; u < QW; u++) {
        m2x[u] = -2.f * cb[(qbase + u) * 3 + 0];
        m2y[u] = -2.f * cb[(qbase + u) * 3 + 1];
        m2z[u] = -2.f * cb[(qbase + u) * 3 + 2];
    }

    float val[QW], thr[QW];
    int idx[QW];
#pragma unroll
    for (int u = 0; u < QW; u++) { val[u] = 3.0e38f; thr[u] = 3.0e38f; idx[u] = -1; }

    for (int c0 = 0; c0 < NPTS; c0 += CCH) {
        __syncthreads();
        for (int t = threadIdx.x; t < CCH; t += 256) {
            float x = cb[(c0 + t) * 3 + 0];
            float y = cb[(c0 + t) * 3 + 1];
            float z = cb[(c0 + t) * 3 + 2];
            sx[t] = x; sy[t] = y; sz[t] = z;
            ss[t] = fmaf(z, z, fmaf(y, y, x * x));
        }
        __syncthreads();

        if (c0 == 0) {
            // seed: force-insert candidates 0..7 once per query -> thr finite
            float ex = 0.f, ey = 0.f, ez = 0.f, es = 0.f;
            if (lane < 8) { ex = sx[lane]; ey = sy[lane]; ez = sz[lane]; es = ss[lane]; }
#pragma unroll
            for (int u = 0; u < QW; u++) {
                float e = fmaf(m2z[u], ez, fmaf(m2y[u], ey, fmaf(m2x[u], ex, es)));
#pragma unroll
                for (int r = 0; r < 8; r++) {
                    float dn = __shfl_sync(full, e, r);
                    float pv = __shfl_up_sync(full, val[u], 1);
                    int   pi = __shfl_up_sync(full, idx[u], 1);
                    unsigned le = __ballot_sync(full, val[u] <= dn);
                    int pos = __popc(le & 0xff);
                    if (lane == pos)                 { val[u] = dn; idx[u] = r; }
                    else if (lane > pos && lane < 8) { val[u] = pv; idx[u] = pi; }
                }
                thr[u] = __shfl_sync(full, val[u], 7);
            }
        }

        for (int j0 = 0; j0 < CCH; j0 += 128) {
            int base = j0 + lane * 4;
            float4 cx = *(const float4*)&sx[base];
            float4 cy = *(const float4*)&sy[base];
            float4 cz = *(const float4*)&sz[base];
            float4 cs = *(const float4*)&ss[base];
            int jb = c0 + j0;                        // warp-uniform
            const bool seeded = (jb == 0) && (lane < 2);   // cands 0..7 already in
#pragma unroll
            for (int u = 0; u < QW; u++) {
                float e0 = fmaf(m2z[u], cz.x, fmaf(m2y[u], cy.x, fmaf(m2x[u], cx.x, cs.x)));
                float e1 = fmaf(m2z[u], cz.y, fmaf(m2y[u], cy.y, fmaf(m2x[u], cx.y, cs.y)));
                float e2 = fmaf(m2z[u], cz.z, fmaf(m2y[u], cy.z, fmaf(m2x[u], cx.z, cs.z)));
                float e3 = fmaf(m2z[u], cz.w, fmaf(m2y[u], cy.w, fmaf(m2x[u], cx.w, cs.w)));
                if (seeded) { e0 = 3.0e38f; e1 = 3.0e38f; e2 = 3.0e38f; e3 = 3.0e38f; }
                float lm = fminf(fminf(e0, e1), fminf(e2, e3));
                if (__any_sync(full, lm < thr[u])) {
                    try_insert4(e0, jb + 0, val[u], idx[u], thr[u]);
                    try_insert4(e1, jb + 1, val[u], idx[u], thr[u]);
                    try_insert4(e2, jb + 2, val[u], idx[u], thr[u]);
                    try_insert4(e3, jb + 3, val[u], idx[u], thr[u]);
                }
            }
        }
    }

    if (lane < KNN) {
#pragma unroll
        for (int u = 0; u < QW; u++)
            out_idx[((size_t)b * NPTS + qbase + u) * KNN + lane] = idx[u];
    }
}

// ---------------- attention over K=8 neighbors (batched k loads, MLP=8) --------
__global__ __launch_bounds__(256) void attn_kernel(const float* __restrict__ coords,
                                                   const float* __restrict__ logg)
{
    const int gq   = blockIdx.x * 8 + (threadIdx.x >> 5);
    const int b    = gq >> 13;
    const int q    = gq & (NPTS - 1);
    const int lane = threadIdx.x & 31;
    const float lg = *logg;
    const float inv_sqrt_c = 0.08838834764831845f;   // 1/sqrt(128)

    float4 qv = *(const float4*)(g_q + (size_t)gq * CH + lane * 4);

    const float* cb = coords + (size_t)b * NPTS * 3;
    const float qx = cb[q * 3 + 0], qy = cb[q * 3 + 1], qz = cb[q * 3 + 2];

    int nb[KNN];
#pragma unroll
    for (int t = 0; t < KNN; t++) nb[t] = g_idx[(size_t)gq * KNN + t];

    // batch all 8 k-row loads up front (MLP=8) before the serial reductions
    float4 kv[KNN];
#pragma unroll
    for (int t = 0; t < KNN; t++)
        kv[t] = *(const float4*)(g_k + ((size_t)b * NPTS + nb[t]) * CH + lane * 4);

    float sc[KNN];
#pragma unroll
    for (int t = 0; t < KNN; t++) {
        float d = qv.x * kv[t].x;
        d = fmaf(qv.y, kv[t].y, d);
        d = fmaf(qv.z, kv[t].z, d);
        d = fmaf(qv.w, kv[t].w, d);
#pragma unroll
        for (int off = 16; off; off >>= 1) d += __shfl_xor_sync(0xffffffffu, d, off);
        float dx = qx - cb[nb[t] * 3 + 0];
        float dy = qy - cb[nb[t] * 3 + 1];
        float dz = qz - cb[nb[t] * 3 + 2];
        float d2 = fmaf(dz, dz, fmaf(dy, dy, dx * dx));
        float dist = (d2 > 0.f) ? sqrtf(d2) : 0.f;     // _safe_norm
        float gw = expf(lg * dist);
        sc[t] = d * inv_sqrt_c * gw;
    }
    float m = sc[0];
#pragma unroll
    for (int t = 1; t < KNN; t++) m = fmaxf(m, sc[t]);
    float ssum = 0.f;
#pragma unroll
    for (int t = 0; t < KNN; t++) { sc[t] = expf(sc[t] - m); ssum += sc[t]; }
    float inv = 1.f / ssum;

    float4 acc = make_float4(0.f, 0.f, 0.f, 0.f);
#pragma unroll
    for (int t = 0; t < KNN; t++) {
        float4 vv = *(const float4*)(g_v + ((size_t)b * NPTS + nb[t]) * CH + lane * 4);
        float wt = sc[t] * inv;
        acc.x = fmaf(wt, vv.x, acc.x);
        acc.y = fmaf(wt, vv.y, acc.y);
        acc.z = fmaf(wt, vv.z, acc.z);
        acc.w = fmaf(wt, vv.w, acc.w);
    }
    // write agg in bf16 hi/lo X-pattern: channels (4l,4l+1) and (4l+2,4l+3)
    unsigned pa = pack_hilo(acc.x), pb = pack_hilo(acc.y);
    unsigned pc = pack_hilo(acc.z), pd = pack_hilo(acc.w);
    g_agg2[(size_t)gq * 64 + lane * 2 + 0] = make_uint4(pa, pa, pb, pb);
    g_agg2[(size_t)gq * 64 + lane * 2 + 1] = make_uint4(pc, pc, pd, pd);
}

// ---------------- launch: fork qkv onto a side stream, overlap with knn --------
extern "C" void kernel_launch(void* const* d_in, const int* in_sizes, int n_in,
                              void* d_out, int out_size)
{
    const float* feats  = (const float*)d_in[0];
    const float* coords = (const float*)d_in[1];
    const float* Wq     = (const float*)d_in[2];
    const float* Wk     = (const float*)d_in[3];
    const float* Wv     = (const float*)d_in[4];
    const float* Wo     = (const float*)d_in[5];
    const float* logg   = (const float*)d_in[6];
    float* out = (float*)d_out;

    int* idx_ptr = nullptr;
    cudaGetSymbolAddress((void**)&idx_ptr, g_idx);

    cudaStream_t s2;
    cudaStreamCreateWithFlags(&s2, cudaStreamNonBlocking);
    cudaEvent_t e_fork, e_join;
    cudaEventCreateWithFlags(&e_fork, cudaEventDisableTiming);
    cudaEventCreateWithFlags(&e_join, cudaEventDisableTiming);

    // fork: qkv runs on s2 concurrently with knn (knn leaves RF room at occ=3)
    cudaEventRecord(e_fork, 0);
    cudaStreamWaitEvent(s2, e_fork, 0);
    qkv_mma_kernel<<<dim3(MTOT / 64, 3), 256, 0, s2>>>(feats, Wq, Wk, Wv);
    cudaEventRecord(e_join, s2);

    // knn on main stream (the long pole; tensor pipe left to qkv)
    knn_kernel<<<dim3(NPTS / 32, BATCH), 256>>>(coords, idx_ptr);

    // join: attn needs both knn (g_idx) and qkv (g_q/g_k/g_v)
    cudaStreamWaitEvent(0, e_join, 0);

    attn_kernel<<<MTOT / 8, 256>>>(coords, logg);
    out_mma_kernel<<<MTOT / 64, 256>>>(Wo, out);

    cudaEventDestroy(e_fork);
    cudaEventDestroy(e_join);
    cudaStreamDestroy(s2);
}

// round 17
// speedup vs baseline: 1.1079x; 1.1079x over previous
#include <cuda_runtime.h>
#include <cuda_bf16.h>
#include <math.h>

#define BATCH 2
#define NPTS  8192
#define CH    128
#define KNN   8
#define MTOT  (BATCH * NPTS)

// ---------------- scratch (no allocations allowed) ----------------
__device__ float g_q[MTOT * CH];
__device__ float g_k[MTOT * CH];
__device__ float g_v[MTOT * CH];
__device__ int   g_idx[MTOT * KNN];
__device__ uint4 g_agg2[MTOT * 64];    // agg split, X-pattern (hi,lo,hi,lo)

// ---------------- fp32 -> (hi,lo) bf16 split helpers ----------------
__device__ __forceinline__ void split_bf16(float x, unsigned short& h, unsigned short& l) {
    __nv_bfloat16 hb = __float2bfloat16(x);
    float hf = __bfloat162float(hb);
    __nv_bfloat16 lb = __float2bfloat16(x - hf);
    h = __bfloat16_as_ushort(hb);
    l = __bfloat16_as_ushort(lb);
}
__device__ __forceinline__ unsigned pack_hilo(float x) {   // X-pattern word (hi,lo)
    unsigned short h, l; split_bf16(x, h, l);
    return ((unsigned)l << 16) | (unsigned)h;
}
__device__ __forceinline__ void pack_w(float x, unsigned& p0, unsigned& p1) { // (hi,hi),(lo,lo)
    unsigned short h, l; split_bf16(x, h, l);
    p0 = ((unsigned)h << 16) | h;
    p1 = ((unsigned)l << 16) | l;
}

// ---------------- tensor-core GEMM 64x128 (qkv; hidden under knn) --------------
template <bool SPLIT_X>
__device__ __forceinline__ void mma_gemm_tile(const void* __restrict__ Xv,
                                              const float* __restrict__ Wf,
                                              float* __restrict__ Y, int m0)
{
    __shared__ __align__(16) unsigned char xs[64 * 144];
    __shared__ __align__(16) unsigned char ws[128 * 144];
    const int tid  = threadIdx.x;
    const int lane = tid & 31;
    const int warp = tid >> 5;
    const int wm   = warp >> 2;
    const int wn   = warp & 3;
    const int g    = lane >> 2;
    const int c4   = lane & 3;

    float acc[2][4][4];
#pragma unroll
    for (int i = 0; i < 2; i++)
#pragma unroll
        for (int t = 0; t < 4; t++)
#pragma unroll
            for (int r = 0; r < 4; r++) acc[i][t][r] = 0.f;

    for (int kc = 0; kc < 8; kc++) {
        __syncthreads();
#pragma unroll
        for (int i = 0; i < 2; i++) {
            int s  = tid + i * 256;
            int r  = s >> 3;
            int f4 = s & 7;
            if (SPLIT_X) {
                const float* X = (const float*)Xv;
                float2 xv = *(const float2*)(X + (size_t)(m0 + r) * CH + kc * 16 + f4 * 2);
                unsigned p0 = pack_hilo(xv.x), p1 = pack_hilo(xv.y);
                *(uint4*)(xs + r * 144 + f4 * 16) = make_uint4(p0, p0, p1, p1);
            } else {
                const uint4* X2 = (const uint4*)Xv;
                *(uint4*)(xs + r * 144 + f4 * 16) = X2[(size_t)(m0 + r) * 64 + kc * 8 + f4];
            }
        }
#pragma unroll
        for (int i = 0; i < 4; i++) {
            int s  = tid + i * 256;
            int r  = s >> 3;
            int f4 = s & 7;
            float2 wv = *(const float2*)(Wf + (size_t)r * CH + kc * 16 + f4 * 2);
            unsigned a0, a1, b0, b1;
            pack_w(wv.x, a0, a1);
            pack_w(wv.y, b0, b1);
            *(uint4*)(ws + r * 144 + f4 * 16) = make_uint4(a0, a1, b0, b1);
        }
        __syncthreads();
#pragma unroll
        for (int ks = 0; ks < 4; ks++) {
            unsigned a[2][4], b[4][2];
#pragma unroll
            for (int i = 0; i < 2; i++)
#pragma unroll
                for (int j = 0; j < 4; j++) {
                    int row = wm * 32 + i * 16 + g + 8 * (j & 1);
                    int off = ks * 32 + (j >> 1) * 16 + c4 * 4;
                    a[i][j] = *(const unsigned*)(xs + row * 144 + off);
                }
#pragma unroll
            for (int t = 0; t < 4; t++)
#pragma unroll
                for (int r = 0; r < 2; r++) {
                    int n   = wn * 32 + t * 8 + g;
                    int off = ks * 32 + r * 16 + c4 * 4;
                    b[t][r] = *(const unsigned*)(ws + n * 144 + off);
                }
#pragma unroll
            for (int i = 0; i < 2; i++)
#pragma unroll
                for (int t = 0; t < 4; t++)
                    asm volatile(
                        "mma.sync.aligned.m16n8k16.row.col.f32.bf16.bf16.f32 "
                        "{%0,%1,%2,%3}, {%4,%5,%6,%7}, {%8,%9}, {%0,%1,%2,%3};"
                        : "+f"(acc[i][t][0]), "+f"(acc[i][t][1]),
                          "+f"(acc[i][t][2]), "+f"(acc[i][t][3])
                        : "r"(a[i][0]), "r"(a[i][1]), "r"(a[i][2]), "r"(a[i][3]),
                          "r"(b[t][0]), "r"(b[t][1]));
        }
    }
#pragma unroll
    for (int i = 0; i < 2; i++)
#pragma unroll
        for (int t = 0; t < 4; t++) {
            int row = m0 + wm * 32 + i * 16 + g;
            int col = wn * 32 + t * 8 + 2 * c4;
            *(float2*)(Y + (size_t)row * CH + col)       = make_float2(acc[i][t][0], acc[i][t][1]);
            *(float2*)(Y + (size_t)(row + 8) * CH + col) = make_float2(acc[i][t][2], acc[i][t][3]);
        }
}

__global__ __launch_bounds__(256) void qkv_mma_kernel(const float* __restrict__ feats,
                                                      const float* __restrict__ Wq,
                                                      const float* __restrict__ Wk,
                                                      const float* __restrict__ Wv)
{
    int w = blockIdx.y;
    const float* W = (w == 0) ? Wq : (w == 1) ? Wk : Wv;
    float* Y = (w == 0) ? g_q : (w == 1) ? g_k : g_v;
    mma_gemm_tile<true>(feats, W, Y, blockIdx.x * 64);
}

// ---------------- out GEMM 64x64 tiles (grid 512 -> better latency hiding) -----
// 8 warps as 2(m) x 4(n); warp tile 32x16 -> acc[2][2][4] (16 regs).
__global__ __launch_bounds__(256) void out_mma_kernel(const float* __restrict__ Wo,
                                                      float* __restrict__ out)
{
    __shared__ __align__(16) unsigned char xs[64 * 144];
    __shared__ __align__(16) unsigned char ws[64 * 144];
    const int tid  = threadIdx.x;
    const int lane = tid & 31;
    const int warp = tid >> 5;
    const int wm   = warp >> 2;       // 0..1 -> rows wm*32
    const int wn   = warp & 3;        // 0..3 -> cols wn*16
    const int g    = lane >> 2;
    const int c4   = lane & 3;
    const int m0   = blockIdx.x * 64;
    const int n0   = blockIdx.y * 64;

    float acc[2][2][4];
#pragma unroll
    for (int i = 0; i < 2; i++)
#pragma unroll
        for (int t = 0; t < 2; t++)
#pragma unroll
            for (int r = 0; r < 4; r++) acc[i][t][r] = 0.f;

    for (int kc = 0; kc < 8; kc++) {
        __syncthreads();
        // X: pre-split uint4 rows (g_agg2); 512 slots, 2 per thread
#pragma unroll
        for (int i = 0; i < 2; i++) {
            int s  = tid + i * 256;
            int r  = s >> 3;
            int f4 = s & 7;
            *(uint4*)(xs + r * 144 + f4 * 16) = g_agg2[(size_t)(m0 + r) * 64 + kc * 8 + f4];
        }
        // W: 64 rows (n0..n0+63), split inline; 512 slots, 2 per thread
#pragma unroll
        for (int i = 0; i < 2; i++) {
            int s  = tid + i * 256;
            int r  = s >> 3;
            int f4 = s & 7;
            float2 wv = *(const float2*)(Wo + (size_t)(n0 + r) * CH + kc * 16 + f4 * 2);
            unsigned a0, a1, b0, b1;
            pack_w(wv.x, a0, a1);
            pack_w(wv.y, b0, b1);
            *(uint4*)(ws + r * 144 + f4 * 16) = make_uint4(a0, a1, b0, b1);
        }
        __syncthreads();
#pragma unroll
        for (int ks = 0; ks < 4; ks++) {
            unsigned a[2][4], b[2][2];
#pragma unroll
            for (int i = 0; i < 2; i++)
#pragma unroll
                for (int j = 0; j < 4; j++) {
                    int row = wm * 32 + i * 16 + g + 8 * (j & 1);
                    int off = ks * 32 + (j >> 1) * 16 + c4 * 4;
                    a[i][j] = *(const unsigned*)(xs + row * 144 + off);
                }
#pragma unroll
            for (int t = 0; t < 2; t++)
#pragma unroll
                for (int r = 0; r < 2; r++) {
                    int n   = wn * 16 + t * 8 + g;
                    int off = ks * 32 + r * 16 + c4 * 4;
                    b[t][r] = *(const unsigned*)(ws + n * 144 + off);
                }
#pragma unroll
            for (int i = 0; i < 2; i++)
#pragma unroll
                for (int t = 0; t < 2; t++)
                    asm volatile(
                        "mma.sync.aligned.m16n8k16.row.col.f32.bf16.bf16.f32 "
                        "{%0,%1,%2,%3}, {%4,%5,%6,%7}, {%8,%9}, {%0,%1,%2,%3};"
                        : "+f"(acc[i][t][0]), "+f"(acc[i][t][1]),
                          "+f"(acc[i][t][2]), "+f"(acc[i][t][3])
                        : "r"(a[i][0]), "r"(a[i][1]), "r"(a[i][2]), "r"(a[i][3]),
                          "r"(b[t][0]), "r"(b[t][1]));
        }
    }
#pragma unroll
    for (int i = 0; i < 2; i++)
#pragma unroll
        for (int t = 0; t < 2; t++) {
            int row = m0 + wm * 32 + i * 16 + g;
            int col = n0 + wn * 16 + t * 8 + 2 * c4;
            *(float2*)(out + (size_t)row * CH + col)       = make_float2(acc[i][t][0], acc[i][t][1]);
            *(float2*)(out + (size_t)(row + 8) * CH + col) = make_float2(acc[i][t][2], acc[i][t][3]);
        }
}

// ---------------- KNN: R14/R15-proven (seeded warm-up, occupancy 4) ------------
#define QW  4
#define CCH 2048

__device__ __forceinline__ void try_insert4(float d2, int base,
                                            float& val, int& idx, float& thr)
{
    const unsigned full = 0xffffffffu;
    unsigned m = __ballot_sync(full, d2 < thr);
    const int lane = threadIdx.x & 31;
    while (m) {
        int src = __ffs(m) - 1;
        m &= m - 1;
        float dn = __shfl_sync(full, d2, src);
        if (dn < thr) {                         // warp-uniform
            int   in = base + (src << 2);
            float pv = __shfl_up_sync(full, val, 1);
            int   pi = __shfl_up_sync(full, idx, 1);
            unsigned le = __ballot_sync(full, val <= dn);
            int pos = __popc(le & 0xff);
            if (lane == pos)                  { val = dn; idx = in; }
            else if (lane > pos && lane < 8)  { val = pv; idx = pi; }
            thr = __shfl_sync(full, val, 7);
        }
    }
}

__global__ __launch_bounds__(256, 4) void knn_kernel(const float* __restrict__ coords,
                                                     int* __restrict__ out_idx)
{
    __shared__ float sx[CCH], sy[CCH], sz[CCH], ss[CCH];
    const unsigned full = 0xffffffffu;
    const int b     = blockIdx.y;
    const int warp  = threadIdx.x >> 5;
    const int lane  = threadIdx.x & 31;
    const int qbase = blockIdx.x * (8 * QW) + warp * QW;
    const float* cb = coords + (size_t)b * NPTS * 3;

    float m2x[QW], m2y[QW], m2z[QW];
#pragma unroll
    for (int u = 0; u < QW; u++) {
        m2x[u] = -2.f * cb[(qbase + u) * 3 + 0];
        m2y[u] = -2.f * cb[(qbase + u) * 3 + 1];
        m2z[u] = -2.f * cb[(qbase + u) * 3 + 2];
    }

    float val[QW], thr[QW];
    int idx[QW];
#pragma unroll
    for (int u = 0; u < QW; u++) { val[u] = 3.0e38f; thr[u] = 3.0e38f; idx[u] = -1; }

    for (int c0 = 0; c0 < NPTS; c0 += CCH) {
        __syncthreads();
        for (int t = threadIdx.x; t < CCH; t += 256) {
            float x = cb[(c0 + t) * 3 + 0];
            float y = cb[(c0 + t) * 3 + 1];
            float z = cb[(c0 + t) * 3 + 2];
            sx[t] = x; sy[t] = y; sz[t] = z;
            ss[t] = fmaf(z, z, fmaf(y, y, x * x));
        }
        __syncthreads();

        if (c0 == 0) {
            // seed: force-insert candidates 0..7 once per query -> thr finite
            float ex = 0.f, ey = 0.f, ez = 0.f, es = 0.f;
            if (lane < 8) { ex = sx[lane]; ey = sy[lane]; ez = sz[lane]; es = ss[lane]; }
#pragma unroll
            for (int u = 0; u < QW; u++) {
                float e = fmaf(m2z[u], ez, fmaf(m2y[u], ey, fmaf(m2x[u], ex, es)));
#pragma unroll
                for (int r = 0; r < 8; r++) {
                    float dn = __shfl_sync(full, e, r);
                    float pv = __shfl_up_sync(full, val[u], 1);
                    int   pi = __shfl_up_sync(full, idx[u], 1);
                    unsigned le = __ballot_sync(full, val[u] <= dn);
                    int pos = __popc(le & 0xff);
                    if (lane == pos)                 { val[u] = dn; idx[u] = r; }
                    else if (lane > pos && lane < 8) { val[u] = pv; idx[u] = pi; }
                }
                thr[u] = __shfl_sync(full, val[u], 7);
            }
        }

        for (int j0 = 0; j0 < CCH; j0 += 128) {
            int base = j0 + lane * 4;
            float4 cx = *(const float4*)&sx[base];
            float4 cy = *(const float4*)&sy[base];
            float4 cz = *(const float4*)&sz[base];
            float4 cs = *(const float4*)&ss[base];
            int jb = c0 + j0;                        // warp-uniform
            const bool seeded = (jb == 0) && (lane < 2);   // cands 0..7 already in
#pragma unroll
            for (int u = 0; u < QW; u++) {
                float e0 = fmaf(m2z[u], cz.x, fmaf(m2y[u], cy.x, fmaf(m2x[u], cx.x, cs.x)));
                float e1 = fmaf(m2z[u], cz.y, fmaf(m2y[u], cy.y, fmaf(m2x[u], cx.y, cs.y)));
                float e2 = fmaf(m2z[u], cz.z, fmaf(m2y[u], cy.z, fmaf(m2x[u], cx.z, cs.z)));
                float e3 = fmaf(m2z[u], cz.w, fmaf(m2y[u], cy.w, fmaf(m2x[u], cx.w, cs.w)));
                if (seeded) { e0 = 3.0e38f; e1 = 3.0e38f; e2 = 3.0e38f; e3 = 3.0e38f; }
                float lm = fminf(fminf(e0, e1), fminf(e2, e3));
                if (__any_sync(full, lm < thr[u])) {
                    try_insert4(e0, jb + 0, val[u], idx[u], thr[u]);
                    try_insert4(e1, jb + 1, val[u], idx[u], thr[u]);
                    try_insert4(e2, jb + 2, val[u], idx[u], thr[u]);
                    try_insert4(e3, jb + 3, val[u], idx[u], thr[u]);
                }
            }
        }
    }

    if (lane < KNN) {
#pragma unroll
        for (int u = 0; u < QW; u++)
            out_idx[((size_t)b * NPTS + qbase + u) * KNN + lane] = idx[u];
    }
}

// ---------------- attention over K=8 neighbors (batched k loads, MLP=8) --------
__global__ __launch_bounds__(256) void attn_kernel(const float* __restrict__ coords,
                                                   const float* __restrict__ logg)
{
    const int gq   = blockIdx.x * 8 + (threadIdx.x >> 5);
    const int b    = gq >> 13;
    const int q    = gq & (NPTS - 1);
    const int lane = threadIdx.x & 31;
    const float lg = *logg;
    const float inv_sqrt_c = 0.08838834764831845f;   // 1/sqrt(128)

    float4 qv = *(const float4*)(g_q + (size_t)gq * CH + lane * 4);

    const float* cb = coords + (size_t)b * NPTS * 3;
    const float qx = cb[q * 3 + 0], qy = cb[q * 3 + 1], qz = cb[q * 3 + 2];

    int nb[KNN];
#pragma unroll
    for (int t = 0; t < KNN; t++) nb[t] = g_idx[(size_t)gq * KNN + t];

    // batch all 8 k-row loads up front (MLP=8) before the serial reductions
    float4 kv[KNN];
#pragma unroll
    for (int t = 0; t < KNN; t++)
        kv[t] = *(const float4*)(g_k + ((size_t)b * NPTS + nb[t]) * CH + lane * 4);

    float sc[KNN];
#pragma unroll
    for (int t = 0; t < KNN; t++) {
        float d = qv.x * kv[t].x;
        d = fmaf(qv.y, kv[t].y, d);
        d = fmaf(qv.z, kv[t].z, d);
        d = fmaf(qv.w, kv[t].w, d);
#pragma unroll
        for (int off = 16; off; off >>= 1) d += __shfl_xor_sync(0xffffffffu, d, off);
        float dx = qx - cb[nb[t] * 3 + 0];
        float dy = qy - cb[nb[t] * 3 + 1];
        float dz = qz - cb[nb[t] * 3 + 2];
        float d2 = fmaf(dz, dz, fmaf(dy, dy, dx * dx));
        float dist = (d2 > 0.f) ? sqrtf(d2) : 0.f;     // _safe_norm
        float gw = expf(lg * dist);
        sc[t] = d * inv_sqrt_c * gw;
    }
    float m = sc[0];
#pragma unroll
    for (int t = 1; t < KNN; t++) m = fmaxf(m, sc[t]);
    float ssum = 0.f;
#pragma unroll
    for (int t = 0; t < KNN; t++) { sc[t] = expf(sc[t] - m); ssum += sc[t]; }
    float inv = 1.f / ssum;

    float4 acc = make_float4(0.f, 0.f, 0.f, 0.f);
#pragma unroll
    for (int t = 0; t < KNN; t++) {
        float4 vv = *(const float4*)(g_v + ((size_t)b * NPTS + nb[t]) * CH + lane * 4);
        float wt = sc[t] * inv;
        acc.x = fmaf(wt, vv.x, acc.x);
        acc.y = fmaf(wt, vv.y, acc.y);
        acc.z = fmaf(wt, vv.z, acc.z);
        acc.w = fmaf(wt, vv.w, acc.w);
    }
    // write agg in bf16 hi/lo X-pattern: channels (4l,4l+1) and (4l+2,4l+3)
    unsigned pa = pack_hilo(acc.x), pb = pack_hilo(acc.y);
    unsigned pc = pack_hilo(acc.z), pd = pack_hilo(acc.w);
    g_agg2[(size_t)gq * 64 + lane * 2 + 0] = make_uint4(pa, pa, pb, pb);
    g_agg2[(size_t)gq * 64 + lane * 2 + 1] = make_uint4(pc, pc, pd, pd);
}

// ---------------- launch: fork qkv onto a side stream, overlap with knn --------
extern "C" void kernel_launch(void* const* d_in, const int* in_sizes, int n_in,
                              void* d_out, int out_size)
{
    const float* feats  = (const float*)d_in[0];
    const float* coords = (const float*)d_in[1];
    const float* Wq     = (const float*)d_in[2];
    const float* Wk     = (const float*)d_in[3];
    const float* Wv     = (const float*)d_in[4];
    const float* Wo     = (const float*)d_in[5];
    const float* logg   = (const float*)d_in[6];
    float* out = (float*)d_out;

    int* idx_ptr = nullptr;
    cudaGetSymbolAddress((void**)&idx_ptr, g_idx);

    cudaStream_t s2;
    cudaStreamCreateWithFlags(&s2, cudaStreamNonBlocking);
    cudaEvent_t e_fork, e_join;
    cudaEventCreateWithFlags(&e_fork, cudaEventDisableTiming);
    cudaEventCreateWithFlags(&e_join, cudaEventDisableTiming);

    // fork: qkv runs on s2 concurrently with knn (harvests knn tail/ramp)
    cudaEventRecord(e_fork, 0);
    cudaStreamWaitEvent(s2, e_fork, 0);
    qkv_mma_kernel<<<dim3(MTOT / 64, 3), 256, 0, s2>>>(feats, Wq, Wk, Wv);
    cudaEventRecord(e_join, s2);

    // knn on main stream (the long pole)
    knn_kernel<<<dim3(NPTS / 32, BATCH), 256>>>(coords, idx_ptr);

    // join: attn needs both knn (g_idx) and qkv (g_q/g_k/g_v)
    cudaStreamWaitEvent(0, e_join, 0);

    attn_kernel<<<MTOT / 8, 256>>>(coords, logg);
    out_mma_kernel<<<dim3(MTOT / 64, 2), 256>>>(Wo, out);

    cudaEventDestroy(e_fork);
    cudaEventDestroy(e_join);
    cudaStreamDestroy(s2);
}